// round 11
// baseline (speedup 1.0000x reference)
#include <cuda_runtime.h>
#include <cuda_fp16.h>
#include <cstdint>
#include <cstddef>

// ============================ problem constants ============================
#define MDIM   16384
#define NDIM   2048
#define KDIM   2048
#define BM     128
#define BN     256
#define BK     64                    // 64 elems along K per stage
#define KITERS 32                    // KDIM / BK
#define TILES_M (MDIM / BM)          // 128
#define TILES_N (NDIM / BN)          // 8
#define NTILES  (TILES_M * TILES_N)  // 1024
#define GRID    148                  // persistent

// smem: A fp16 staging 2 slots (128 rows x 128 B = 16 KB each); B 3 stages (256 rows x 128 B)
#define A_SLOT      16384
#define B_BASE      32768
#define B_STAGE     32768
#define SMEM_BYTES  (B_BASE + 3 * B_STAGE)     // 131072

// ============================ scratch (no allocs allowed) ============================
__device__ uint4  g_xa4[(size_t)MDIM * KDIM / 16];  // 32 MB int8 acts in {-1,0,1}, 16B-aligned
__device__ __half g_wq[(size_t)NDIM * KDIM];        // 8 MB fp16 quantized+rram weights

// ============================ helpers ============================
__device__ __forceinline__ uint32_t smem_u32(const void* p) {
    uint32_t a;
    asm("{ .reg .u64 t; cvta.to.shared.u64 t, %1; cvt.u32.u64 %0, t; }"
        : "=r"(a) : "l"(p));
    return a;
}
__device__ __forceinline__ void cp16(uint32_t dst, const void* src) {
    asm volatile("cp.async.cg.shared.global [%0], [%1], 16;"
                 :: "r"(dst), "l"(src) : "memory");
}
__device__ __forceinline__ void sts128(uint32_t addr, uint32_t r0, uint32_t r1,
                                       uint32_t r2, uint32_t r3) {
    asm volatile("st.shared.v4.b32 [%0], {%1,%2,%3,%4};"
                 :: "r"(addr), "r"(r0), "r"(r1), "r"(r2), "r"(r3) : "memory");
}
__device__ __forceinline__ void ldm_x4(uint32_t* r, uint32_t addr) {
    asm volatile("ldmatrix.sync.aligned.m8n8.x4.shared.b16 {%0,%1,%2,%3}, [%4];"
                 : "=r"(r[0]), "=r"(r[1]), "=r"(r[2]), "=r"(r[3]) : "r"(addr));
}
__device__ __forceinline__ void hmma(float* c, const uint32_t* a,
                                     uint32_t b0, uint32_t b1) {
    asm volatile(
        "mma.sync.aligned.m16n8k16.row.col.f32.f16.f16.f32 "
        "{%0,%1,%2,%3}, {%4,%5,%6,%7}, {%8,%9}, {%0,%1,%2,%3};"
        : "+f"(c[0]), "+f"(c[1]), "+f"(c[2]), "+f"(c[3])
        : "r"(a[0]), "r"(a[1]), "r"(a[2]), "r"(a[3]), "r"(b0), "r"(b1));
}
// two SIGNED bytes (bits [sh,sh+8) and [sh+8,sh+16) of w) -> packed half2.
// NOTE: plain `char` is UNSIGNED on aarch64 — must use `signed char`.
__device__ __forceinline__ uint32_t s8_to_h2(uint32_t w, int sh) {
    int b0 = (int)(signed char)(w >> sh);
    int b1 = (int)(signed char)(w >> (sh + 8));
    __half2 h = __halves2half2(__int2half_rn(b0), __int2half_rn(b1));
    return *reinterpret_cast<uint32_t*>(&h);
}

// ============================ quantize kernels ============================
__device__ __forceinline__ uint32_t terni(float v) {
    return v > 0.33f ? 1u : (v < -0.33f ? 0xFFu : 0u);   // int8 {1,-1,0} as byte
}
__device__ __forceinline__ float ternw(float v) {
    return v > 0.2f ? 0.6f : (v < -0.2f ? -0.6f : 0.0f);
}
__device__ __forceinline__ uint32_t pack4(float4 f) {
    return terni(f.x) | (terni(f.y) << 8) | (terni(f.z) << 16) | (terni(f.w) << 24);
}

__global__ void __launch_bounds__(256) qx_kernel(const float* __restrict__ x) {
    size_t i = (size_t)blockIdx.x * 256 + threadIdx.x;   // 16 elems / thread
    const float4* p = reinterpret_cast<const float4*>(x) + i * 4;
    uint4 v;
    v.x = pack4(p[0]);
    v.y = pack4(p[1]);
    v.z = pack4(p[2]);
    v.w = pack4(p[3]);
    g_xa4[i] = v;
}

__global__ void __launch_bounds__(256) qw_kernel(const float* __restrict__ w,
                                                 const float* __restrict__ rv) {
    size_t i = (size_t)blockIdx.x * 256 + threadIdx.x;
    const float4* pw = reinterpret_cast<const float4*>(w) + i * 2;
    const float4* pr = reinterpret_cast<const float4*>(rv) + i * 2;
    float4 wa = pw[0], wb = pw[1];
    float4 ra = pr[0], rb = pr[1];
    __half2 h0 = __floats2half2_rn(ternw(wa.x) + ra.x, ternw(wa.y) + ra.y);
    __half2 h1 = __floats2half2_rn(ternw(wa.z) + ra.z, ternw(wa.w) + ra.w);
    __half2 h2 = __floats2half2_rn(ternw(wb.x) + rb.x, ternw(wb.y) + rb.y);
    __half2 h3 = __floats2half2_rn(ternw(wb.z) + rb.z, ternw(wb.w) + rb.w);
    uint4 v;
    v.x = *reinterpret_cast<uint32_t*>(&h0);
    v.y = *reinterpret_cast<uint32_t*>(&h1);
    v.z = *reinterpret_cast<uint32_t*>(&h2);
    v.w = *reinterpret_cast<uint32_t*>(&h3);
    reinterpret_cast<uint4*>(g_wq)[i] = v;
}

// ============================ GEMM kernel (persistent, int8-A feed) ============================
__global__ void __launch_bounds__(256, 1)
gemm_kernel(float* __restrict__ out) {
    extern __shared__ __align__(1024) char smem[];
    const uint32_t sb = smem_u32(smem);
    const int tid  = threadIdx.x;
    const int lane = tid & 31;
    const int wid  = tid >> 5;
    const int wm   = wid >> 2;       // 0..1 : 64-row strip (M)     [R5 layout]
    const int wn   = wid & 3;        // 0..3 : 64-col strip (N)
    const int bid  = blockIdx.x;

    // A feed: thread -> (row 0..127, half hh of 64 int8)
    const int r  = tid >> 1;
    const int hh = tid & 1;
    const uint32_t arsw = ((uint32_t)(r & 7)) << 4;

    // B feed: R5 geometry (8 x 16B per thread per stage)
    const int rA = tid >> 3;                              // 0..31
    const int ch = tid & 7;
    const uint32_t col_sw = ((uint32_t)ch * 16) ^ (((uint32_t)rA & 7) << 4);

    // ldmatrix addressing (SW128) — R5 verbatim
    const uint32_t kxor     = (uint32_t)(lane & 7) << 4;
    const uint32_t rowA_off = (uint32_t)(wm * 64 + (lane & 15)) * 128;
    const uint32_t rowB_off = (uint32_t)(wn * 64 + (lane & 15)) * 128;
    const uint32_t khi      = (uint32_t)(lane & 16);

    const int L = (NTILES - bid + GRID - 1) / GRID;
    const int V = L * KITERS;

    uint4 lb0, lb1;                                       // 32 int8 of one A row-half
    auto ldgA = [&](int v) {
        const int t  = bid + (v >> 5) * GRID;
        const int k  = v & 31;
        const int m0 = (t >> 3) * BM;
        const char* src = (const char*)g_xa4
                        + (size_t)(m0 + r) * KDIM + (size_t)k * BK + hh * 32;
        lb0 = __ldg((const uint4*)src);
        lb1 = __ldg((const uint4*)src + 1);
    };
    auto stsA = [&](int v) {
        const uint32_t slot = sb + (uint32_t)(v & 1) * A_SLOT + (uint32_t)r * 128;
        const uint32_t c0 = (uint32_t)(hh * 64);
        sts128(slot + ((c0 +  0) ^ arsw),
               s8_to_h2(lb0.x, 0), s8_to_h2(lb0.x, 16),
               s8_to_h2(lb0.y, 0), s8_to_h2(lb0.y, 16));
        sts128(slot + ((c0 + 16) ^ arsw),
               s8_to_h2(lb0.z, 0), s8_to_h2(lb0.z, 16),
               s8_to_h2(lb0.w, 0), s8_to_h2(lb0.w, 16));
        sts128(slot + ((c0 + 32) ^ arsw),
               s8_to_h2(lb1.x, 0), s8_to_h2(lb1.x, 16),
               s8_to_h2(lb1.y, 0), s8_to_h2(lb1.y, 16));
        sts128(slot + ((c0 + 48) ^ arsw),
               s8_to_h2(lb1.z, 0), s8_to_h2(lb1.z, 16),
               s8_to_h2(lb1.w, 0), s8_to_h2(lb1.w, 16));
    };
    auto produceB = [&](int v) {
        const int t  = bid + (v >> 5) * GRID;
        const int k  = v & 31;
        const int n0 = (t & 7) * BN;
        const uint32_t st = sb + B_BASE + (uint32_t)(v % 3) * B_STAGE;
        const __half* pb = g_wq + (size_t)(n0 + rA) * KDIM + ch * 8 + (size_t)k * BK;
        #pragma unroll
        for (int n = 0; n < 8; n++)                       // B: 256 rows
            cp16(st + (uint32_t)(rA + n * 32) * 128 + col_sw,
                 pb + (size_t)n * 32 * KDIM);
        asm volatile("cp.async.commit_group;" ::: "memory");
    };

    float acc[4][4][2][4];                                // 128 regs  [R5]
    #pragma unroll
    for (int mf = 0; mf < 4; mf++)
        #pragma unroll
        for (int p = 0; p < 4; p++)
            #pragma unroll
            for (int h = 0; h < 2; h++)
                acc[mf][p][h][0] = acc[mf][p][h][1] =
                acc[mf][p][h][2] = acc[mf][p][h][3] = 0.f;

    ldgA(0);
    produceB(0);
    produceB(1);

    for (int v = 0; v < V; v++) {
        asm volatile("cp.async.wait_group 1;" ::: "memory");
        stsA(v);
        __syncthreads();
        if (v + 1 < V) ldgA(v + 1);
        if (v + 2 < V) produceB(v + 2);
        else asm volatile("cp.async.commit_group;" ::: "memory");

        const uint32_t aslot = sb + (uint32_t)(v & 1) * A_SLOT;
        const uint32_t bbase = sb + B_BASE + (uint32_t)(v % 3) * B_STAGE;
        #pragma unroll
        for (int ks = 0; ks < 4; ks++) {
            const uint32_t colk = ((uint32_t)(ks * 32) + khi) ^ kxor;
            uint32_t a[4][4];
            #pragma unroll
            for (int mf = 0; mf < 4; mf++)
                ldm_x4(a[mf], aslot + rowA_off + (uint32_t)mf * 2048 + colk);
            uint32_t b[4][4];
            #pragma unroll
            for (int p = 0; p < 4; p++)
                ldm_x4(b[p], bbase + rowB_off + (uint32_t)p * 2048 + colk);
            #pragma unroll
            for (int mf = 0; mf < 4; mf++) {
                #pragma unroll
                for (int p = 0; p < 4; p++) {
                    hmma(acc[mf][p][0], a[mf], b[p][0], b[p][2]);  // n [p*16+0, +8)
                    hmma(acc[mf][p][1], a[mf], b[p][1], b[p][3]);  // n [p*16+8, +16)
                }
            }
        }

        if ((v & 31) == 31) {
            const int t  = bid + (v >> 5) * GRID;
            const int m0 = (t >> 3) * BM;
            const int n0 = (t & 7) * BN;
            const int rbase = m0 + wm * 64 + (lane >> 2);
            const int cbase = n0 + wn * 64 + (lane & 3) * 2;
            #pragma unroll
            for (int mf = 0; mf < 4; mf++) {
                #pragma unroll
                for (int p = 0; p < 4; p++) {
                    #pragma unroll
                    for (int h = 0; h < 2; h++) {
                        const int col = cbase + p * 16 + h * 8;
                        float* o0 = out + (size_t)(rbase + mf * 16) * NDIM + col;
                        float* o1 = out + (size_t)(rbase + mf * 16 + 8) * NDIM + col;
                        *reinterpret_cast<float2*>(o0) =
                            make_float2(acc[mf][p][h][0] * 0.5f,
                                        acc[mf][p][h][1] * 0.5f);
                        *reinterpret_cast<float2*>(o1) =
                            make_float2(acc[mf][p][h][2] * 0.5f,
                                        acc[mf][p][h][3] * 0.5f);
                        acc[mf][p][h][0] = acc[mf][p][h][1] = 0.f;
                        acc[mf][p][h][2] = acc[mf][p][h][3] = 0.f;
                    }
                }
            }
        }
    }
}

// ============================ host launcher ============================
extern "C" void kernel_launch(void* const* d_in, const int* in_sizes, int n_in,
                              void* d_out, int out_size) {
    (void)in_sizes; (void)n_in; (void)out_size;
    const float* x  = (const float*)d_in[0];
    const float* w  = (const float*)d_in[1];
    const float* rv = (const float*)d_in[2];
    float* out = (float*)d_out;

    qx_kernel<<<8192, 256>>>(x);         // 8192*256*16 = 16384*2048
    qw_kernel<<<2048, 256>>>(w, rv);     // 2048*256*8  = 2048*2048

    static bool configured = false;
    if (!configured) {
        cudaFuncSetAttribute((const void*)gemm_kernel,
                             cudaFuncAttributeMaxDynamicSharedMemorySize, SMEM_BYTES);
        configured = true;
    }
    gemm_kernel<<<GRID, 256, SMEM_BYTES>>>(out);
}